// round 1
// baseline (speedup 1.0000x reference)
#include <cuda_runtime.h>
#include <math.h>

#define NEGV  (-1e30f)
#define MAXL  128
#define MAXS  (2*MAXL + 1)     // 257
#define BLOCK 288              // >= MAXS, multiple of 32

// per-batch partial total scores (deterministic reduction)
__device__ float g_partial[256];

__device__ __forceinline__ float lae(float a, float b) {
    // logaddexp; exact enough with fast intrinsics (arg of __logf in [1,2])
    float m = fmaxf(a, b);
    float d = fabsf(a - b);
    return m + __logf(1.0f + __expf(-d));
}

__global__ void __launch_bounds__(BLOCK, 1)
ctc_fwd(const float* __restrict__ lp,      // [T, B, V] log-probs
        const int*   __restrict__ targets, // [B, L] flat
        const int*   __restrict__ ilen,    // [B]
        int T, int B, int V, int L)
{
    const int b   = blockIdx.x;
    const int tid = threadIdx.x;
    const int S   = 2 * L + 1;

    __shared__ float sh_alpha[2][MAXS + 2];   // state s at index s+2; [0..1] = NEG pad
    __shared__ float sh_e[2][MAXL + 1];       // [parity][0]=blank, [1+j]=label j
    __shared__ int   sh_lab[MAXL];
    __shared__ unsigned char sh_skip[MAXL];

    int Tb = ilen[b];
    if (Tb > T) Tb = T;

    if (tid < L) sh_lab[tid] = targets[b * L + tid];
    for (int s = tid; s < MAXS + 2; s += BLOCK) {
        sh_alpha[0][s] = NEGV;
        sh_alpha[1][s] = NEGV;
    }
    __syncthreads();
    if (tid < L) sh_skip[tid] = (tid >= 1 && sh_lab[tid] != sh_lab[tid - 1]) ? 1 : 0;

    // loader role: tid<L loads label tid's emission, tid==L loads blank
    const bool loader = (tid <= L);
    int vidx = 0, eidx = 0;
    if (loader) {
        vidx = (tid < L) ? sh_lab[tid] : 0;
        eidx = (tid < L) ? (tid + 1)   : 0;
    }
    const size_t strideT = (size_t)B * (size_t)V;
    const float* base = lp + (size_t)b * (size_t)V;

    // prologue: emissions for t=0 and t=1 to shared, prefetch t=2 into reg
    if (loader) {
        sh_e[0][eidx] = base[vidx];                               // t = 0
        if (1 < Tb) sh_e[1][eidx] = base[strideT + vidx];         // t = 1
    }
    float r = NEGV;
    if (loader && 2 < Tb) r = base[2 * strideT + vidx];           // t = 2
    __syncthreads();

    // alpha0: only states 0 (blank) and 1 (first label) are live
    if (tid == 0) sh_alpha[0][2 + 0] = sh_e[0][0];
    if (tid == 1) sh_alpha[0][2 + 1] = sh_e[0][1];
    __syncthreads();

    // main sequential recursion: ONE barrier per time step
    for (int t = 1; t < Tb; ++t) {
        const int pc = t & 1;        // parity of alpha/e buffers for time t
        const int pp = pc ^ 1;       // previous

        // stage prefetched emissions for t+1 (written buffer != buffer read below)
        if (loader && (t + 1) < Tb) sh_e[(t + 1) & 1][eidx] = r;
        // issue prefetch for t+2 (consumed two iterations from now)
        if (loader && (t + 2) < Tb) r = base[(size_t)(t + 2) * strideT + vidx];

        if (tid < S) {
            const int s = tid;
            float a0 = sh_alpha[pp][2 + s];     // alpha[s]
            float a1 = sh_alpha[pp][1 + s];     // alpha[s-1] (pad -> NEG)
            float v  = lae(a0, a1);
            if (s & 1) {
                const int j = s >> 1;           // label index
                if (sh_skip[j]) v = lae(v, sh_alpha[pp][s]);  // alpha[s-2]
                v += sh_e[pc][1 + j];
            } else {
                v += sh_e[pc][0];               // blank emission
            }
            sh_alpha[pc][2 + s] = v;
        }
        __syncthreads();
    }

    if (tid == 0) {
        const int pf = (Tb - 1) & 1;
        float tot = lae(sh_alpha[pf][2 + S - 1], sh_alpha[pf][2 + S - 2]);
        g_partial[b] = tot;
    }
}

__global__ void ctc_reduce(float* __restrict__ out, int B) {
    if (threadIdx.x == 0) {
        float s = 0.0f;
        for (int b = 0; b < B; ++b) s += g_partial[b];   // fixed order: deterministic
        out[0] = -s;
    }
}

extern "C" void kernel_launch(void* const* d_in, const int* in_sizes, int n_in,
                              void* d_out, int out_size)
{
    const float* lp      = (const float*)d_in[0];   // log_probs [T,B,V] f32
    const int*   targets = (const int*)  d_in[1];   // [B*L] i32
    const int*   ilen    = (const int*)  d_in[2];   // [B] i32
    // d_in[3] = target_lengths (all == L), unused

    const int B = in_sizes[2];
    const int L = in_sizes[1] / B;
    const int V = 1000;                              // fixed problem shape
    const int T = (int)((long long)in_sizes[0] / ((long long)B * V));

    ctc_fwd<<<B, BLOCK>>>(lp, targets, ilen, T, B, V, L);
    ctc_reduce<<<1, 32>>>((float*)d_out, B);
}

// round 2
// speedup vs baseline: 3.3842x; 3.3842x over previous
#include <cuda_runtime.h>
#include <math.h>

#define NEGV  (-1e30f)
#define MAXL  128
#define MAXS  (2*MAXL + 1)     // 257
#define BLOCK 288              // >= MAXS, multiple of 32
#define PF    8                // emission ring depth (power of 2)

__device__ float g_partial[256];

__device__ __forceinline__ float lae2(float a, float b) {
    float m = fmaxf(a, b);
    return m + __logf(__expf(a - m) + __expf(b - m));
}
__device__ __forceinline__ float lae3(float a, float b, float c) {
    float m = fmaxf(fmaxf(a, b), c);
    return m + __logf(__expf(a - m) + __expf(b - m) + __expf(c - m));
}

__device__ __forceinline__ unsigned smem_u32(const void* p) {
    return (unsigned)__cvta_generic_to_shared(p);
}
__device__ __forceinline__ void cp4(unsigned dst, const float* src) {
    asm volatile("cp.async.ca.shared.global [%0], [%1], 4;\n" :: "r"(dst), "l"(src));
}
__device__ __forceinline__ void cp_commit() {
    asm volatile("cp.async.commit_group;\n");
}
__device__ __forceinline__ void cp_wait6() {
    asm volatile("cp.async.wait_group 6;\n");
}

__global__ void __launch_bounds__(BLOCK, 1)
ctc_fwd(const float* __restrict__ lp,      // [T, B, V] log-probs
        const int*   __restrict__ targets, // [B, L] flat
        const int*   __restrict__ ilen,    // [B]
        int T, int B, int V, int L)
{
    const int b   = blockIdx.x;
    const int tid = threadIdx.x;
    const int S   = 2 * L + 1;

    __shared__ float sh_alpha[2][MAXS + 2];   // state s at index s+2; [0..1] = NEG pad
    __shared__ float sh_e[PF][MAXL + 1];      // [slot][0]=blank, [1+j]=label j
    __shared__ int   sh_lab[MAXL];

    int Tb = ilen[b];
    if (Tb > T) Tb = T;

    if (tid < L) sh_lab[tid] = targets[b * L + tid];
    for (int s = tid; s < MAXS + 2; s += BLOCK) {
        sh_alpha[0][s] = NEGV;
        sh_alpha[1][s] = NEGV;
    }
    __syncthreads();

    // ---- per-thread constants (branchless inner loop) ----
    const int  s      = tid;
    const bool active = (s < S);
    const bool odd    = (s & 1) != 0;
    int  eo   = 0;       // emission index within sh_e row
    bool skip = false;   // s-2 transition allowed
    if (active && odd) {
        const int j = s >> 1;
        eo   = 1 + j;
        skip = (j >= 1) && (sh_lab[j] != sh_lab[j - 1]);
    }

    // ---- loader role: tid<L loads label tid's emission, tid==L loads blank ----
    const bool loader = (tid <= L);
    const float* gsrc = nullptr;
    unsigned sh_dst0 = 0;
    if (loader) {
        const int vv = (tid < L) ? sh_lab[tid] : 0;
        const int ee = (tid < L) ? (tid + 1)   : 0;
        gsrc    = lp + (size_t)b * (size_t)V + vv;
        sh_dst0 = smem_u32(&sh_e[0][ee]);
    }
    const size_t   strideT    = (size_t)B * (size_t)V;
    const unsigned ringStride = (MAXL + 1) * sizeof(float);

    // ---- prologue: issue times 0..7 as 8 groups; wait_group(6) -> times 0,1 done
    #pragma unroll
    for (int t0 = 0; t0 < PF; ++t0) {
        if (loader && t0 < Tb) cp4(sh_dst0 + (unsigned)t0 * ringStride,
                                   gsrc + (size_t)t0 * strideT);
        cp_commit();
    }
    cp_wait6();
    __syncthreads();

    // alpha0: only states 0 (blank) and 1 (first label) are live
    if (tid == 0) sh_alpha[0][2 + 0] = sh_e[0][0];
    if (tid == 1) sh_alpha[0][2 + 1] = sh_e[0][1];
    __syncthreads();

    // ---- main sequential recursion: ONE barrier per time step ----
    for (int t = 1; t < Tb; ++t) {
        const int pc = t & 1;
        const int pp = pc ^ 1;

        // pipeline: issue time t+7 (slot (t-1)&7, last read at iter t-1 -> safe),
        // then ensure time t+1 is complete before this iteration's end barrier.
        {
            const int tf = t + 7;
            if (loader && tf < Tb) cp4(sh_dst0 + (unsigned)(tf & (PF - 1)) * ringStride,
                                       gsrc + (size_t)tf * strideT);
            cp_commit();
            cp_wait6();
        }

        if (active) {
            const float a0 = sh_alpha[pp][2 + s];           // alpha[s]
            const float a1 = sh_alpha[pp][1 + s];           // alpha[s-1] (pad -> NEG)
            const float a2r = sh_alpha[pp][0 + s];          // alpha[s-2] (pad -> NEG)
            const float a2 = skip ? a2r : NEGV;
            const float v  = lae3(a0, a1, a2) + sh_e[t & (PF - 1)][eo];
            sh_alpha[pc][2 + s] = v;
        }
        __syncthreads();
    }

    if (tid == 0) {
        const int pf_ = (Tb - 1) & 1;
        g_partial[b] = lae2(sh_alpha[pf_][2 + S - 1], sh_alpha[pf_][2 + S - 2]);
    }
}

__global__ void ctc_reduce(float* __restrict__ out, int B) {
    // fixed reduction tree: deterministic
    const int lane = threadIdx.x;          // 32 threads
    float v = 0.0f;
    for (int i = lane; i < B; i += 32) v += g_partial[i];
    #pragma unroll
    for (int off = 16; off > 0; off >>= 1)
        v += __shfl_down_sync(0xFFFFFFFFu, v, off);
    if (lane == 0) out[0] = -v;
}

extern "C" void kernel_launch(void* const* d_in, const int* in_sizes, int n_in,
                              void* d_out, int out_size)
{
    const float* lp      = (const float*)d_in[0];   // log_probs [T,B,V] f32
    const int*   targets = (const int*)  d_in[1];   // [B*L] i32
    const int*   ilen    = (const int*)  d_in[2];   // [B] i32
    // d_in[3] = target_lengths (all == L), unused

    const int B = in_sizes[2];
    const int L = in_sizes[1] / B;
    const int V = 1000;                              // fixed problem shape
    const int T = (int)((long long)in_sizes[0] / ((long long)B * V));

    ctc_fwd<<<B, BLOCK>>>(lp, targets, ilen, T, B, V, L);
    ctc_reduce<<<1, 32>>>((float*)d_out, B);
}

// round 3
// speedup vs baseline: 4.4246x; 1.3074x over previous
#include <cuda_runtime.h>
#include <math.h>

#define NEGV  (-1e30f)
#define MAXL  128
#define NPAIR (MAXL + 2)       // pairs 0..128 (+pad)
#define NW    6
#define BLOCK (NW * 32)        // 192 threads
#define OWN   24               // owned pairs per warp
#define HALO  8                // halo pairs == steps per round
#define EROW  132              // floats per emission ring row (pad)
#define RSLOT 32               // ring slots (4 groups of 8)

__device__ float g_partial[256];

__device__ __forceinline__ float lae2(float a, float b) {
    float m = fmaxf(a, b);
    return m + __logf(1.0f + __expf(fminf(a, b) - m));
}

__device__ __forceinline__ unsigned smem_u32(const void* p) {
    return (unsigned)__cvta_generic_to_shared(p);
}
__device__ __forceinline__ void cp4(unsigned dst, const float* src) {
    asm volatile("cp.async.ca.shared.global [%0], [%1], 4;\n" :: "r"(dst), "l"(src));
}
__device__ __forceinline__ void cp_commit() { asm volatile("cp.async.commit_group;\n"); }
__device__ __forceinline__ void cp_wait2()  { asm volatile("cp.async.wait_group 2;\n"); }

__global__ void __launch_bounds__(BLOCK, 1)
ctc_fwd(const float* __restrict__ lp,      // [T, B, V] log-probs
        const int*   __restrict__ targets, // [B, L]
        const int*   __restrict__ ilen,    // [B]
        int T, int B, int V, int L)
{
    const int b    = blockIdx.x;
    const int tid  = threadIdx.x;
    const int w    = tid >> 5;
    const int lane = tid & 31;

    __shared__ float sh_e[RSLOT][EROW];   // [slot][0]=blank, [1+j]=label j
    __shared__ float sh_pa[2][NPAIR];     // even-state alpha per pair (double buf)
    __shared__ float sh_po[2][NPAIR];     // odd-state alpha per pair
    __shared__ int   sh_lab[MAXL];

    int Tb = ilen[b];
    if (Tb > T) Tb = T;

    if (tid < L) sh_lab[tid] = targets[b * L + tid];
    __syncthreads();

    // ---- per-lane pair assignment: pair = 24*w + lane - 8 (lanes 0..7 = halo) ----
    const int  pair      = OWN * w + lane - HALO;          // -8 .. 135
    const int  jc        = min(max(pair, 0), L - 1);       // clamped label index
    const bool odd_valid = (pair >= 0 && pair < L);        // odd state 2j+1 exists
    bool skip = false;
    if (pair >= 1 && pair < L) skip = (sh_lab[pair] != sh_lab[pair - 1]);

    // ---- loader role: tid<L loads label tid's emission, tid==L loads blank ----
    const bool loader = (tid <= L);
    const float* gsrc = nullptr;
    unsigned dst0 = 0;
    if (loader) {
        const int vv = (tid < L) ? sh_lab[tid] : 0;
        const int ee = (tid < L) ? (tid + 1)   : 0;
        gsrc = lp + (size_t)b * (size_t)V + vv;
        dst0 = smem_u32(&sh_e[0][ee]);
    }
    const size_t   strideT = (size_t)B * (size_t)V;
    const unsigned rowB    = EROW * sizeof(float);

    // ---- prologue: issue emission groups 0..2 (times 0..23), 3 groups in flight
    #pragma unroll
    for (int g = 0; g < 3; ++g) {
        if (loader) {
            #pragma unroll
            for (int i = 0; i < 8; ++i) {
                const int t = 8 * g + i;
                if (t < Tb) cp4(dst0 + (unsigned)(t & (RSLOT - 1)) * rowB,
                                gsrc + (size_t)t * strideT);
            }
        }
        cp_commit();
    }
    cp_wait2();          // group 0 complete
    __syncthreads();     // visible to all threads

    // ---- alpha at t=0: only states 0 (blank) and 1 (label 0) live ----
    float a_even = NEGV, a_odd = NEGV;
    if (pair == 0) { a_even = sh_e[0][0]; a_odd = sh_e[0][1]; }

    // ---- rounds of 8 steps; ONE barrier per round ----
    const int R = (Tb + 7) >> 3;      // covers steps t=1..Tb-1
    for (int r = 0; r < R; ++r) {
        // halo refresh from previous round's buffer (round 0: registers already valid)
        if (r > 0 && lane < HALO && pair >= 0) {
            a_even = sh_pa[(r - 1) & 1][pair];
            a_odd  = sh_po[(r - 1) & 1][pair];
        }

        const int tg = 8 * (r + 3);   // prefetch group base time (3 rounds ahead)
        #pragma unroll
        for (int i = 0; i < 8; ++i) {
            const int t = 8 * r + i;
            // interleave one prefetch issue per step
            if (loader && (tg + i) < Tb)
                cp4(dst0 + (unsigned)((tg + i) & (RSLOT - 1)) * rowB,
                    gsrc + (size_t)(tg + i) * strideT);

            float po = __shfl_up_sync(0xFFFFFFFFu, a_odd, 1);   // alpha[2j-1]
            if (pair == 0) po = NEGV;
            // even state 2j <- {2j, 2j-1}
            float me = fmaxf(a_even, po);
            float ne = me + __logf(1.0f + __expf(fminf(a_even, po) - me));
            // odd state 2j+1 <- {2j+1, 2j, 2j-1 if skip}
            float a2 = skip ? po : NEGV;
            float mo = fmaxf(fmaxf(a_odd, a_even), a2);
            float no = mo + __logf(__expf(a_odd - mo) + __expf(a_even - mo) +
                                   __expf(a2 - mo));
            const int slot = t & (RSLOT - 1);
            ne += sh_e[slot][0];          // blank emission (broadcast)
            no += sh_e[slot][1 + jc];     // label emission
            if (t >= 1 && t < Tb) {       // skip t=0; freeze past Tb
                a_even = ne;
                a_odd  = odd_valid ? no : NEGV;
            }
        }

        // publish owned pairs for next round's halo
        if (lane >= HALO && pair <= L) {
            sh_pa[r & 1][pair] = a_even;
            sh_po[r & 1][pair] = a_odd;
        }
        cp_commit();
        cp_wait2();       // next round's emission group complete
        __syncthreads();
    }

    // final: states S-2=255 (pair 127 odd, warp5 lane 15), S-1=256 (pair 128 even, lane 16)
    if (w == NW - 1) {
        float v255 = __shfl_sync(0xFFFFFFFFu, a_odd,  15);
        float v256 = __shfl_sync(0xFFFFFFFFu, a_even, 16);
        if (lane == 0) g_partial[b] = lae2(v255, v256);
    }
}

__global__ void ctc_reduce(float* __restrict__ out, int B) {
    const int lane = threadIdx.x;          // 32 threads; fixed tree: deterministic
    float v = 0.0f;
    for (int i = lane; i < B; i += 32) v += g_partial[i];
    #pragma unroll
    for (int off = 16; off > 0; off >>= 1)
        v += __shfl_down_sync(0xFFFFFFFFu, v, off);
    if (lane == 0) out[0] = -v;
}

extern "C" void kernel_launch(void* const* d_in, const int* in_sizes, int n_in,
                              void* d_out, int out_size)
{
    const float* lp      = (const float*)d_in[0];   // log_probs [T,B,V] f32
    const int*   targets = (const int*)  d_in[1];   // [B*L] i32
    const int*   ilen    = (const int*)  d_in[2];   // [B] i32
    // d_in[3] = target_lengths (all == L), unused

    const int B = in_sizes[2];
    const int L = in_sizes[1] / B;
    const int V = 1000;                              // fixed problem shape
    const int T = (int)((long long)in_sizes[0] / ((long long)B * V));

    ctc_fwd<<<B, BLOCK>>>(lp, targets, ilen, T, B, V, L);
    ctc_reduce<<<1, 32>>>((float*)d_out, B);
}